// round 1
// baseline (speedup 1.0000x reference)
#include <cuda_runtime.h>
#include <math.h>

// ---------------- problem constants ----------------
#define NPIX   4096          // 64*64
#define NMODE  64            // 8*8 retained rfft2 modes
#define NSEQ   64            // b*s
#define NCH    256           // heads*hid

// ---------------- scratch (device globals; no runtime alloc) ----------------
__device__ float2 g_vf [NSEQ*4*NMODE];        // rfft2(v) low modes
__device__ float2 g_qf [NSEQ*NCH*NMODE];
__device__ float2 g_kf [NSEQ*NCH*NMODE];
__device__ float2 g_vlf[NSEQ*NCH*NMODE];
__device__ float  g_l2 [16*32*32];
__device__ float  g_A  [16*32*32];
__device__ float2 g_uf [NSEQ*NCH*NMODE];      // attention output spectrum, [n][ch][m]
__device__ float2 g_uf2[NSEQ*32*NMODE];       // u1 spectral-conv output
__device__ float2 g_sk1[NSEQ*32*NMODE];       // s1 skip spectrum
__device__ float  g_x1 [NSEQ*32*NPIX];        // spatial x1 (needed: gelu + conv1x1 skip)
__device__ float2 g_x1f[NSEQ*32*NMODE];       // rfft2(x1) low modes

__device__ __forceinline__ void make_tw(float* twc, float* tws, int tid){
  if (tid < 64){
    float a = 0.09817477042468103f * (float)tid;   // 2*pi/64
    twc[tid] = cosf(a); tws[tid] = sinf(a);
  }
}

// ---------------- K1: truncated forward DFT of v -> g_vf ----------------
// grid 256 = (n*4+cin), 256 threads. Separable: cols (kx) then rows (ky).
__global__ void k_fwd_v(const float* __restrict__ v){
  __shared__ float  sx[NPIX];
  __shared__ float2 st[512];           // [r][kx]
  __shared__ float twc[64], tws[64];
  int tid = threadIdx.x;
  make_tw(twc,tws,tid);
  const float* x = v + blockIdx.x * NPIX;
  for (int i=tid;i<NPIX;i+=256) sx[i]=x[i];
  __syncthreads();
  for (int id=tid; id<512; id+=256){
    int r = id>>3, kx = id&7;
    const float* row = sx + r*64;
    float re=0.f, im=0.f;
    #pragma unroll 8
    for (int c=0;c<64;c++){
      int j = (kx*c)&63; float a = row[c];
      re += a*twc[j]; im -= a*tws[j];
    }
    st[id] = make_float2(re,im);
  }
  __syncthreads();
  if (tid < 64){
    int ky=tid>>3, kx=tid&7;
    float re=0.f, im=0.f;
    #pragma unroll 8
    for (int r=0;r<64;r++){
      float2 t = st[r*8+kx];
      int j=(ky*r)&63; float c=twc[j], s=tws[j];
      re += t.x*c + t.y*s;           // t * e^{-i theta}
      im += t.y*c - t.x*s;
    }
    g_vf[blockIdx.x*64 + tid] = make_float2(re,im);
  }
}

// ---------------- K2: q/k/val spectral weight multiply ----------------
// grid (64 n, 3 tensor), 256 threads
__global__ void k_qkv(const float* __restrict__ qwr, const float* __restrict__ qwi,
                      const float* __restrict__ kwr, const float* __restrict__ kwi,
                      const float* __restrict__ vwr, const float* __restrict__ vwi){
  int n = blockIdx.x;
  const float *wr, *wi; float2* dst;
  if (blockIdx.y==0){wr=qwr;wi=qwi;dst=g_qf;}
  else if (blockIdx.y==1){wr=kwr;wi=kwi;dst=g_kf;}
  else {wr=vwr;wi=vwi;dst=g_vlf;}
  __shared__ float2 sv[256];
  int tid=threadIdx.x;
  sv[tid] = g_vf[n*256+tid];
  __syncthreads();
  for (int out=tid; out<16384; out+=256){
    int co = out>>6, m = out&63;
    float re=0.f, im=0.f;
    #pragma unroll
    for (int ci=0;ci<4;ci++){
      float2 a = sv[ci*64+m];
      int wix = ((ci<<8)+co)*64 + m;
      float br=wr[wix], bi=wi[wix];
      re += a.x*br - a.y*bi;
      im += a.x*bi + a.y*br;
    }
    dst[n*16384+out] = make_float2(re,im);
  }
}

// ---------------- K3a: l2 via Parseval-weighted mode dot ----------------
// grid (16 head, 4 sgroup), 256 threads; thread = (s_local, t)
__global__ void k_l2(){
  int bh = blockIdx.x, sg = blockIdx.y;
  int b = bh>>3, hh = bh&7;
  int base = (b*32 + hh*4) * 16384;     // head block: 4 consecutive n rows, all 256 ch
  const float2* Qh = g_qf + base;
  const float2* Kh = g_kf + base;
  __shared__ float2 sq[8*64];
  __shared__ float2 sk[64*33];          // [m][t], padded
  int tid=threadIdx.x;
  int sl = tid>>5, t = tid&31;
  float acc = 0.f;
  for (int d=0; d<32; d++){
    __syncthreads();
    for (int i=tid;i<512;i+=256){
      int s_ = i>>6, m = i&63;
      sq[i] = Qh[(sg*8+s_)*2048 + d*64 + m];
    }
    for (int i=tid;i<2048;i+=256){
      int t_ = i>>6, m = i&63;
      sk[m*33+t_] = Kh[t_*2048 + d*64 + m];
    }
    __syncthreads();
    #pragma unroll
    for (int m=0;m<64;m++){
      float2 q = sq[sl*64+m];
      float2 k = sk[m*33+t];
      if (m==0) acc += q.x*k.x;                        // (0,0): Re*Re only
      else {
        float wm = ((m&7)==0) ? 0.5f : 2.0f;           // kx=0 col halved; rest doubled
        acc += wm*(q.x*k.x + q.y*k.y);
      }
    }
  }
  // scale(0.5) * dx^2(1/4096) * Parseval(1/4096)
  g_l2[bh*1024 + (sg*8+sl)*32 + t] = acc * 2.9802322387695312e-8f;
}

// ---------------- K3b: softmax over t ----------------
__global__ void k_softmax(){
  int bh = blockIdx.x;
  int tid=threadIdx.x, warp=tid>>5, lane=tid&31;
  for (int rr=0; rr<4; rr++){
    int s = warp*4+rr;
    float x = g_l2[bh*1024 + s*32 + lane];
    float mx = x;
    #pragma unroll
    for (int o=16;o;o>>=1) mx = fmaxf(mx, __shfl_xor_sync(0xffffffffu, mx, o));
    float e = expf(x-mx);
    float sm = e;
    #pragma unroll
    for (int o=16;o;o>>=1) sm += __shfl_xor_sync(0xffffffffu, sm, o);
    g_A[bh*1024 + s*32 + lane] = e/sm;
  }
}

// ---------------- K3c: U = A @ val (in mode space), remap to [n][ch][m] ----------------
// grid (16 head, 4 dgroup), 512 threads; thread owns one (d,m) column for all 32 s
__global__ void k_attn_u(){
  int bh = blockIdx.x, dg = blockIdx.y;
  int b = bh>>3, hh = bh&7;
  int base = (b*32 + hh*4)*16384;
  const float2* Vh = g_vlf + base;
  __shared__ float sA[32*33];
  int tid = threadIdx.x;
  for (int i=tid;i<1024;i+=512) sA[(i>>5)*33 + (i&31)] = g_A[bh*1024 + i];
  __syncthreads();
  int d = dg*8 + (tid>>6);
  int m = tid&63;
  float2 acc[32];
  #pragma unroll
  for (int s=0;s<32;s++) acc[s]=make_float2(0.f,0.f);
  const float2* vp = Vh + d*64 + m;
  for (int t=0;t<32;t++){
    float2 vv = vp[t*2048];
    #pragma unroll
    for (int s=0;s<32;s++){
      float a = sA[s*33+t];
      acc[s].x += a*vv.x;
      acc[s].y += a*vv.y;
    }
  }
  int chb = hh*32 + d;
  #pragma unroll
  for (int s=0;s<32;s++)
    g_uf[((b*32+s)*256 + chb)*64 + m] = acc[s];
}

// ---------------- K4: per-mode GEMM 256->32 (u1, with P projection) + s1 skip ----------------
// grid 64 (mode m), 512 threads; thread = (n-group, co), 4 n each
__global__ void k_u1(const float* __restrict__ u1wr, const float* __restrict__ u1wi,
                     const float* __restrict__ s1w){
  int m = blockIdx.x;
  int tid = threadIdx.x;
  int co = tid&31, ng = tid>>5;   // ng in 0..15 -> n = ng*4 + k
  __shared__ float2 sAa[64*32];   // [n][cil]
  __shared__ float2 sB [32*32];   // [cil][co]
  __shared__ float  sS [32*32];   // [cil][co]
  float2 c4[4]; float2 s4[4];
  #pragma unroll
  for (int k=0;k<4;k++){ c4[k]=make_float2(0.f,0.f); s4[k]=make_float2(0.f,0.f); }
  bool kx0 = ((m&7)==0);
  bool m0  = (m==0);
  for (int ci0=0; ci0<256; ci0+=32){
    __syncthreads();
    for (int i=tid;i<2048;i+=512){
      int n_ = i>>5, cil = i&31;
      sAa[i] = g_uf[(n_*256 + ci0 + cil)*64 + m];
    }
    for (int i=tid;i<1024;i+=512){
      int cil = i>>5, co_ = i&31;
      int widx = ((ci0+cil)*32 + co_)*64 + m;
      sB[i] = make_float2(u1wr[widx], u1wi[widx]);
      sS[i] = s1w[co_*256 + ci0 + cil];
    }
    __syncthreads();
    #pragma unroll 4
    for (int cil=0; cil<32; cil++){
      float2 bw = sB[cil*32+co];
      float  swv= sS[cil*32+co];
      #pragma unroll
      for (int k=0;k<4;k++){
        float2 a = sAa[(ng*4+k)*32 + cil];
        // skip path uses raw uf (synthesis is linear in F)
        s4[k].x += a.x*swv; s4[k].y += a.y*swv;
        // spectral-conv path uses P(uf) = rfft2(irfft2(uf)) low modes
        float ax = a.x, ay = a.y;
        if (m0) ay = 0.f;
        else if (kx0){ ax *= 0.5f; ay *= 0.5f; }
        c4[k].x += ax*bw.x - ay*bw.y;
        c4[k].y += ax*bw.y + ay*bw.x;
      }
    }
  }
  #pragma unroll
  for (int k=0;k<4;k++){
    int n_ = ng*4+k;
    g_uf2[(n_*32+co)*64 + m] = c4[k];
    g_sk1[(n_*32+co)*64 + m] = s4[k];
  }
}

// ---------------- K5: synthesis + gelu + skip + bias -> x1; fused forward DFT -> x1f ----------
// grid 2048 = (n*32+co), 256 threads
__global__ void k_x1(const float* __restrict__ s1b){
  int bid = blockIdx.x;
  int co = bid & 31;
  int tid = threadIdx.x;
  __shared__ float twc[64], tws[64];
  __shared__ float2 sF1[64], sF2[64];
  __shared__ float2 T1[512], T2[512];
  __shared__ float  sx[NPIX];
  __shared__ float2 stf[512];
  make_tw(twc,tws,tid);
  if (tid < 64){
    sF1[tid] = g_uf2[bid*64+tid];
    sF2[tid] = g_sk1[bid*64+tid];
  }
  __syncthreads();
  // synthesis stage1 (rows): T[r][kx] = sum_ky F[ky,kx] e^{+2pi i ky r/64}
  for (int id=tid; id<512; id+=256){
    int r=id>>3, kx=id&7;
    float re1=0.f,im1=0.f,re2=0.f,im2=0.f;
    #pragma unroll
    for (int ky=0;ky<8;ky++){
      int j=(ky*r)&63; float c=twc[j], s=tws[j];
      float2 f1=sF1[ky*8+kx], f2=sF2[ky*8+kx];
      re1 += f1.x*c - f1.y*s; im1 += f1.x*s + f1.y*c;
      re2 += f2.x*c - f2.y*s; im2 += f2.x*s + f2.y*c;
    }
    T1[id]=make_float2(re1,im1);
    T2[id]=make_float2(re2,im2);
  }
  __syncthreads();
  float bias = s1b[co];
  const float inv = 1.0f/4096.0f;
  float* gx = g_x1 + bid*NPIX;
  for (int p=tid; p<NPIX; p+=256){
    int r=p>>6, c=p&63;
    const float2* t1 = T1 + r*8;
    const float2* t2 = T2 + r*8;
    float y1 = t1[0].x, y2 = t2[0].x;   // irfft drops Im of kx=0 bin
    #pragma unroll
    for (int kx=1;kx<8;kx++){
      int j=(kx*c)&63; float cc=twc[j], ss=tws[j];
      y1 += 2.f*(t1[kx].x*cc - t1[kx].y*ss);
      y2 += 2.f*(t2[kx].x*cc - t2[kx].y*ss);
    }
    y1 *= inv; y2 *= inv;
    float g = 0.5f*y1*(1.f+erff(y1*0.70710678118654752f));  // exact gelu
    float val = g + y2 + bias;
    sx[p] = val;
    gx[p] = val;
  }
  __syncthreads();
  // forward DFT of x1 (x1 not band-limited after gelu)
  for (int id=tid; id<512; id+=256){
    int r=id>>3, kx=id&7;
    const float* row = sx + r*64;
    float re=0.f,im=0.f;
    #pragma unroll 8
    for (int c=0;c<64;c++){
      int j=(kx*c)&63; float a=row[c];
      re += a*twc[j]; im -= a*tws[j];
    }
    stf[id]=make_float2(re,im);
  }
  __syncthreads();
  if (tid<64){
    int ky=tid>>3, kx=tid&7;
    float re=0.f,im=0.f;
    #pragma unroll 8
    for (int r=0;r<64;r++){
      float2 t = stf[r*8+kx];
      int j=(ky*r)&63; float c=twc[j], s=tws[j];
      re += t.x*c + t.y*s;
      im += t.y*c - t.x*s;
    }
    g_x1f[bid*64+tid]=make_float2(re,im);
  }
}

// ---------------- K7: u2 spectral conv + synthesis + spatial conv1x1 skip -> output -------
// grid 64 (n), 256 threads
__global__ void k_final(const float* __restrict__ u2wr, const float* __restrict__ u2wi,
                        const float* __restrict__ s2w, const float* __restrict__ s2b,
                        float* __restrict__ out){
  int n = blockIdx.x;
  int tid = threadIdx.x;
  __shared__ float twc[64], tws[64];
  __shared__ float2 sXF[32*64];
  __shared__ float2 sF[4*64];
  __shared__ float2 T[4*512];
  __shared__ float swm[128];
  __shared__ float sbv[4];
  make_tw(twc,tws,tid);
  for (int i=tid;i<2048;i+=256) sXF[i] = g_x1f[n*2048 + i];
  if (tid<128) swm[tid]=s2w[tid];
  if (tid<4)   sbv[tid]=s2b[tid];
  __syncthreads();
  { // x2f[o][m], one output per thread
    int o = tid>>6, m = tid&63;
    float re=0.f,im=0.f;
    #pragma unroll 8
    for (int ci=0;ci<32;ci++){
      float2 a = sXF[ci*64+m];
      int wix = ((ci*4+o)<<6)+m;
      float br=u2wr[wix], bi=u2wi[wix];
      re += a.x*br - a.y*bi;
      im += a.x*bi + a.y*br;
    }
    sF[(tid>>6)*64 + (tid&63)] = make_float2(re,im);
  }
  __syncthreads();
  for (int id=tid; id<2048; id+=256){
    int o=id>>9, rem=id&511, r=rem>>3, kx=rem&7;
    float re=0.f,im=0.f;
    #pragma unroll
    for (int ky=0;ky<8;ky++){
      int j=(ky*r)&63; float c=twc[j], s=tws[j];
      float2 f=sF[o*64+ky*8+kx];
      re += f.x*c - f.y*s; im += f.x*s + f.y*c;
    }
    T[id]=make_float2(re,im);
  }
  __syncthreads();
  const float inv=1.f/4096.f;
  const float* gx = g_x1 + n*32*NPIX;
  float* go = out + n*4*NPIX;
  for (int p=tid;p<NPIX;p+=256){
    int r=p>>6, c=p&63;
    float xv[32];
    #pragma unroll 8
    for (int ci=0;ci<32;ci++) xv[ci]=gx[ci*NPIX+p];
    #pragma unroll
    for (int o=0;o<4;o++){
      const float2* t = T + o*512 + r*8;
      float y = t[0].x;
      #pragma unroll
      for (int kx=1;kx<8;kx++){
        int j=(kx*c)&63;
        y += 2.f*(t[kx].x*twc[j] - t[kx].y*tws[j]);
      }
      y *= inv;
      float sk = sbv[o];
      #pragma unroll 8
      for (int ci=0;ci<32;ci++) sk += xv[ci]*swm[o*32+ci];
      go[o*NPIX+p] = y + sk;
    }
  }
}

// ---------------- launch ----------------
extern "C" void kernel_launch(void* const* d_in, const int* in_sizes, int n_in,
                              void* d_out, int out_size){
  const float* v   = (const float*)d_in[0];
  const float* qwr = (const float*)d_in[1];
  const float* qwi = (const float*)d_in[2];
  const float* kwr = (const float*)d_in[3];
  const float* kwi = (const float*)d_in[4];
  const float* vwr = (const float*)d_in[5];
  const float* vwi = (const float*)d_in[6];
  const float* u1wr= (const float*)d_in[7];
  const float* u1wi= (const float*)d_in[8];
  const float* u2wr= (const float*)d_in[9];
  const float* u2wi= (const float*)d_in[10];
  const float* s1w = (const float*)d_in[11];
  const float* s1b = (const float*)d_in[12];
  const float* s2w = (const float*)d_in[13];
  const float* s2b = (const float*)d_in[14];

  k_fwd_v  <<<256, 256>>>(v);
  k_qkv    <<<dim3(64,3), 256>>>(qwr,qwi,kwr,kwi,vwr,vwi);
  k_l2     <<<dim3(16,4), 256>>>();
  k_softmax<<<16, 256>>>();
  k_attn_u <<<dim3(16,4), 512>>>();
  k_u1     <<<64, 512>>>(u1wr,u1wi,s1w);
  k_x1     <<<2048, 256>>>(s1b);
  k_final  <<<64, 256>>>(u2wr,u2wi,s2w,s2b,(float*)d_out);
}

// round 2
// speedup vs baseline: 1.3515x; 1.3515x over previous
#include <cuda_runtime.h>
#include <math.h>

#define NPIX   4096
#define NMODE  64
#define NSEQ   64
#define NCH    256

typedef unsigned long long u64;

__device__ __forceinline__ u64 pk(float a, float b){
  u64 r; asm("mov.b64 %0,{%1,%2};" : "=l"(r) : "f"(a), "f"(b)); return r;
}
__device__ __forceinline__ float2 up(u64 v){
  float2 r; asm("mov.b64 {%0,%1},%2;" : "=f"(r.x), "=f"(r.y) : "l"(v)); return r;
}
__device__ __forceinline__ void fma2(u64& d, u64 a, u64 b){
  asm("fma.rn.f32x2 %0,%1,%2,%0;" : "+l"(d) : "l"(a), "l"(b));
}

// ---------------- scratch ----------------
__device__ float2 g_vf [NSEQ*4*NMODE];
__device__ float2 g_qf [NSEQ*NCH*NMODE];
__device__ float2 g_kf [NSEQ*NCH*NMODE];
__device__ float2 g_vlf[NSEQ*NCH*NMODE];
__device__ float  g_A  [16*32*32];
__device__ float2 g_uf [NSEQ*NCH*NMODE];
__device__ float2 g_uf2[NSEQ*32*NMODE];
__device__ float2 g_sk1[NSEQ*32*NMODE];
__device__ float  g_x1 [NSEQ*32*NPIX];
__device__ float2 g_x1f[NSEQ*32*NMODE];

__device__ __forceinline__ void tw_init(float* twc, float* tws, u64* twp, int tid){
  if (tid < 64){
    float a = 0.09817477042468103f * (float)tid;
    float cc = cosf(a), ss = sinf(a);
    twc[tid]=cc; tws[tid]=ss;
    if (twp) twp[tid]=pk(cc,ss);
  }
}

// ---------------- K1: forward DFT of v (column-register scheme) ----------------
// grid 64 (n), 256 thr = 4 ci x 64 columns
__global__ __launch_bounds__(256) void k_fwd_v(const float* __restrict__ v){
  __shared__ float twc[64], tws[64];
  __shared__ u64   twp[64];
  __shared__ float2 sC[4*8*64];
  int tid=threadIdx.x, chv=tid>>6, c=tid&63;
  tw_init(twc,tws,twp,tid);
  __syncthreads();
  const float* x = v + (size_t)(blockIdx.x*4 + chv)*NPIX + c;
  u64 C2[8];
  #pragma unroll
  for (int ky=0;ky<8;ky++) C2[ky]=0ull;
  for (int r=0;r<64;r++){
    float xv = __ldg(x + r*64);
    u64 x2 = pk(xv,xv);
    #pragma unroll
    for (int ky=0;ky<8;ky++) fma2(C2[ky], x2, twp[(ky*r)&63]);
  }
  #pragma unroll
  for (int ky=0;ky<8;ky++) sC[(chv*8+ky)*64 + c] = up(C2[ky]);
  __syncthreads();
  {
    int md = tid&63, ky2 = md>>3, kx = md&7;
    float re=0.f, im=0.f;
    const float2* Crow = sC + (chv*8+ky2)*64;
    #pragma unroll 8
    for (int cc=0;cc<64;cc++){
      float2 t = Crow[cc];
      int j=(kx*cc)&63;
      re += t.x*twc[j] - t.y*tws[j];
      im -= t.y*twc[j] + t.x*tws[j];
    }
    g_vf[(size_t)(blockIdx.x*4+chv)*64 + md] = make_float2(re,im);
  }
}

// ---------------- K2: q/k/val spectral weight multiply ----------------
__global__ __launch_bounds__(256) void k_qkv(const float* __restrict__ qwr, const float* __restrict__ qwi,
                      const float* __restrict__ kwr, const float* __restrict__ kwi,
                      const float* __restrict__ vwr, const float* __restrict__ vwi){
  int n = blockIdx.x;
  const float *wr, *wi; float2* dst;
  if (blockIdx.y==0){wr=qwr;wi=qwi;dst=g_qf;}
  else if (blockIdx.y==1){wr=kwr;wi=kwi;dst=g_kf;}
  else {wr=vwr;wi=vwi;dst=g_vlf;}
  __shared__ float2 sv[256];
  int tid=threadIdx.x;
  sv[tid] = g_vf[n*256+tid];
  __syncthreads();
  for (int out=tid; out<16384; out+=256){
    int co = out>>6, m = out&63;
    float re=0.f, im=0.f;
    #pragma unroll
    for (int ci=0;ci<4;ci++){
      float2 a = sv[ci*64+m];
      int wix = ((ci<<8)+co)*64 + m;
      float br=wr[wix], bi=wi[wix];
      re += a.x*br - a.y*bi;
      im += a.x*bi + a.y*br;
    }
    dst[(size_t)n*16384+out] = make_float2(re,im);
  }
}

// ---------------- K3: l2 (Parseval mode dot) + fused softmax ----------------
// grid (16 head, 4 sgroup), 256 thr = 8 warps; warp w handles m-slice [w*8, w*8+8)
__global__ __launch_bounds__(256) void k_l2s(){
  int bh = blockIdx.x, sg = blockIdx.y;
  int b = bh>>3, hh = bh&7;
  const float2* Qh = g_qf + (size_t)(b*32 + hh*4)*16384;
  const float2* Kh = g_kf + (size_t)(b*32 + hh*4)*16384;
  __shared__ float2 sq[512];        // [s8][m64]
  __shared__ float2 skw[64*33];     // weighted K, [m][t]
  __shared__ float  red[8*256];     // [warp][s][t]
  int tid=threadIdx.x, w=tid>>5, t=tid&31;
  u64 acc[8];
  #pragma unroll
  for (int s=0;s<8;s++) acc[s]=0ull;
  for (int d=0; d<32; d++){
    __syncthreads();
    for (int i=tid;i<512;i+=256){
      int s_=i>>6, m=i&63;
      sq[i] = Qh[(size_t)(sg*8+s_)*2048 + d*64 + m];
    }
    for (int i=tid;i<2048;i+=256){
      int t_=i>>6, m=i&63;
      float2 k = Kh[(size_t)t_*2048 + d*64 + m];
      float wm = ((m&7)==0) ? 0.5f : 2.0f;
      if (m==0){ skw[t_] = make_float2(k.x, 0.f); }
      else     { skw[m*33+t_] = make_float2(k.x*wm, k.y*wm); }
    }
    __syncthreads();
    int m0 = w*8;
    #pragma unroll
    for (int mm=0;mm<8;mm++){
      int m = m0+mm;
      u64 kv = *(const u64*)&skw[m*33+t];
      #pragma unroll
      for (int s=0;s<8;s++){
        u64 qv = *(const u64*)&sq[s*64+m];
        fma2(acc[s], qv, kv);
      }
    }
  }
  #pragma unroll
  for (int s=0;s<8;s++){ float2 a=up(acc[s]); red[w*256 + s*32 + t] = a.x + a.y; }
  __syncthreads();
  {
    int s = tid>>5, lane = tid&31;
    float l2 = 0.f;
    #pragma unroll
    for (int ww=0;ww<8;ww++) l2 += red[ww*256 + s*32 + lane];
    l2 *= 2.9802322387695312e-8f;    // 0.5 * dx^2 * 1/N (Parseval)
    float mx = l2;
    #pragma unroll
    for (int o=16;o;o>>=1) mx = fmaxf(mx, __shfl_xor_sync(0xffffffffu, mx, o));
    float e = expf(l2-mx);
    float sm = e;
    #pragma unroll
    for (int o=16;o;o>>=1) sm += __shfl_xor_sync(0xffffffffu, sm, o);
    g_A[bh*1024 + (sg*8+s)*32 + lane] = e/sm;
  }
}

// ---------------- K4: U = A @ val ----------------
// grid (16 head, 8 dgroup), 256 thr: thread = (d in 4, m in 64)
__global__ __launch_bounds__(256) void k_attn_u(){
  int bh = blockIdx.x, dg = blockIdx.y;
  int b = bh>>3, hh = bh&7;
  const float2* Vh = g_vlf + (size_t)(b*32 + hh*4)*16384;
  __shared__ float2 sA2[1024];      // (a,a) packed, [s][t]
  int tid = threadIdx.x;
  for (int i=tid;i<1024;i+=256){ float a = g_A[bh*1024 + i]; sA2[i]=make_float2(a,a); }
  __syncthreads();
  int d = dg*4 + (tid>>6);
  int m = tid&63;
  u64 acc[32];
  #pragma unroll
  for (int s=0;s<32;s++) acc[s]=0ull;
  const float2* vp = Vh + d*64 + m;
  for (int t=0;t<32;t++){
    u64 vv = *(const u64*)(vp + (size_t)t*2048);
    #pragma unroll
    for (int s=0;s<32;s++) fma2(acc[s], *(const u64*)&sA2[s*32+t], vv);
  }
  int chb = hh*32 + d;
  #pragma unroll
  for (int s=0;s<32;s++)
    g_uf[(size_t)((b*32+s)*256 + chb)*64 + m] = up(acc[s]);
}

// ---------------- K5: per-mode GEMM 256->32 (u1 with P projection) + s1 skip ----------------
// grid (64 m, 4 nsplit), 256 thr: co = tid>>3 (32), ngp = tid&7 (8 n-pairs)
__global__ __launch_bounds__(256) void k_u1(const float* __restrict__ u1wr, const float* __restrict__ u1wi,
                     const float* __restrict__ s1w){
  int m = blockIdx.x, ns = blockIdx.y;
  bool kx0 = ((m&7)==0), m0 = (m==0);
  int tid = threadIdx.x;
  int co = tid>>3, ngp = tid&7;
  __shared__ float2 sA [32*16];   // [cil][ng]
  __shared__ float2 sW [32*32];   // (wr,wi) P-scaled
  __shared__ float2 sWs[32*32];   // (-wi,wr) P-scaled (0 at m==0)
  __shared__ float  sS [32*32];
  u64 cv0=0ull, cv1=0ull, sv0=0ull, sv1=0ull;
  float pm = (!m0 && kx0) ? 0.5f : 1.0f;
  for (int ci0=0; ci0<256; ci0+=32){
    __syncthreads();
    #pragma unroll
    for (int k=0;k<2;k++){
      int idx = tid + k*256;
      int cil = idx>>4, ng = idx&15;
      sA[cil*16+ng] = g_uf[(size_t)((ns*16+ng)*256 + ci0+cil)*64 + m];
    }
    #pragma unroll
    for (int k=0;k<4;k++){
      int idx = tid + k*256;
      int cil = idx>>5, co_ = idx&31;
      int widx = ((ci0+cil)*32 + co_)*64 + m;
      float wr = u1wr[widx]*pm, wi = u1wi[widx]*pm;
      sW[idx]  = make_float2(wr, wi);
      sWs[idx] = m0 ? make_float2(0.f,0.f) : make_float2(-wi, wr);
      sS[idx]  = s1w[co_*256 + ci0+cil];
    }
    __syncthreads();
    #pragma unroll 4
    for (int cil=0; cil<32; cil++){
      u64 a0v = *(const u64*)&sA[cil*16 + ngp*2];
      u64 a1v = *(const u64*)&sA[cil*16 + ngp*2 + 1];
      u64 w2  = *(const u64*)&sW [cil*32+co];
      u64 w2s = *(const u64*)&sWs[cil*32+co];
      float sw = sS[cil*32+co];
      u64 sw2 = pk(sw,sw);
      float2 a0 = up(a0v), a1 = up(a1v);
      u64 ax0 = pk(a0.x,a0.x), ay0 = pk(a0.y,a0.y);
      u64 ax1 = pk(a1.x,a1.x), ay1 = pk(a1.y,a1.y);
      fma2(cv0, ax0, w2); fma2(cv0, ay0, w2s);
      fma2(cv1, ax1, w2); fma2(cv1, ay1, w2s);
      fma2(sv0, sw2, a0v);
      fma2(sv1, sw2, a1v);
    }
  }
  int n0 = ns*16 + ngp*2;
  g_uf2[(size_t)(n0*32+co)*64+m]     = up(cv0);
  g_uf2[(size_t)((n0+1)*32+co)*64+m] = up(cv1);
  g_sk1[(size_t)(n0*32+co)*64+m]     = up(sv0);
  g_sk1[(size_t)((n0+1)*32+co)*64+m] = up(sv1);
}

// ---------------- K6: synthesis + gelu + skip -> x1, fused forward DFT -> x1f ----------------
// grid 512 (4 channels each), 256 thr = 4 ch x 64 columns; U in registers
__global__ __launch_bounds__(256) void k_x1(const float* __restrict__ s1b){
  __shared__ float twc[64], tws[64];
  __shared__ u64   twp[64];
  __shared__ float2 sF1[256], sF2[256];
  __shared__ float2 sC[4*8*64];
  int tid=threadIdx.x, chv=tid>>6, c=tid&63;
  int ch = blockIdx.x*4 + chv;
  tw_init(twc,tws,twp,tid);
  sF1[tid] = g_uf2[(size_t)blockIdx.x*256 + tid];
  sF2[tid] = g_sk1[(size_t)blockIdx.x*256 + tid];
  __syncthreads();
  u64 U1p[8], U2p[8];
  #pragma unroll
  for (int ky=0;ky<8;ky++){
    float2 f1=sF1[chv*64+ky*8], f2=sF2[chv*64+ky*8];
    float u1x=f1.x, u1y=f1.y, u2x=f2.x, u2y=f2.y;
    #pragma unroll
    for (int kx=1;kx<8;kx++){
      int j=(kx*c)&63; float tc=twc[j], ts=tws[j];
      f1=sF1[chv*64+ky*8+kx]; f2=sF2[chv*64+ky*8+kx];
      u1x += 2.f*(f1.x*tc - f1.y*ts); u1y += 2.f*(f1.x*ts + f1.y*tc);
      u2x += 2.f*(f2.x*tc - f2.y*ts); u2y += 2.f*(f2.x*ts + f2.y*tc);
    }
    U1p[ky]=pk(u1x,u1y); U2p[ky]=pk(u2x,u2y);
  }
  u64 C2[8];
  #pragma unroll
  for (int ky=0;ky<8;ky++) C2[ky]=0ull;
  float bias = s1b[ch&31];
  float* gx = g_x1 + (size_t)ch*NPIX + c;
  const float inv = 1.0f/4096.0f;
  for (int r=0;r<64;r++){
    u64 wp[8];
    #pragma unroll
    for (int ky=0;ky<8;ky++) wp[ky]=twp[(ky*r)&63];
    u64 a1=0ull, a2=0ull;
    #pragma unroll
    for (int ky=0;ky<8;ky++){ fma2(a1,U1p[ky],wp[ky]); fma2(a2,U2p[ky],wp[ky]); }
    float2 v1=up(a1), v2=up(a2);
    float y1=(v1.x - v1.y)*inv;
    float y2=(v2.x - v2.y)*inv;
    float g = 0.5f*y1*(1.f+erff(y1*0.70710678118654752f));
    float val = g + y2 + bias;
    gx[r*64] = val;
    u64 vp2 = pk(val,val);
    #pragma unroll
    for (int ky=0;ky<8;ky++) fma2(C2[ky], vp2, wp[ky]);
  }
  #pragma unroll
  for (int ky=0;ky<8;ky++) sC[(chv*8+ky)*64 + c] = up(C2[ky]);
  __syncthreads();
  {
    int md=tid&63, ky2=md>>3, kx=md&7;
    float re=0.f, im=0.f;
    const float2* Crow = sC + (chv*8+ky2)*64;
    #pragma unroll 8
    for (int cc=0;cc<64;cc++){
      float2 t = Crow[cc];
      int j=(kx*cc)&63;
      re += t.x*twc[j] - t.y*tws[j];
      im -= t.y*twc[j] + t.x*tws[j];
    }
    g_x1f[(size_t)ch*64 + md] = make_float2(re,im);
  }
}

// ---------------- K7: u2 spectral conv + synthesis + conv1x1 skip ----------------
// grid (64 n, 2 pixel-halves), 256 thr
__global__ __launch_bounds__(256) void k_final(const float* __restrict__ u2wr, const float* __restrict__ u2wi,
                        const float* __restrict__ s2w, const float* __restrict__ s2b,
                        float* __restrict__ out){
  int n = blockIdx.x;
  __shared__ float twc[64], tws[64];
  __shared__ u64   twp[64];
  __shared__ float2 sXF[2048];
  __shared__ float2 sF[256];
  __shared__ float2 T[4*512];
  __shared__ u64 sw2[128];
  __shared__ float sbv[4];
  int tid=threadIdx.x;
  tw_init(twc,tws,twp,tid);
  for (int i=tid;i<2048;i+=256) sXF[i] = g_x1f[(size_t)n*2048 + i];
  if (tid<128){ float w=s2w[tid]; sw2[tid]=pk(w,w); }
  if (tid<4) sbv[tid]=s2b[tid];
  __syncthreads();
  {
    int o=tid>>6, m=tid&63;
    float re=0.f, im=0.f;
    #pragma unroll 8
    for (int ci=0;ci<32;ci++){
      float2 a = sXF[ci*64+m];
      int wix = ((ci*4+o)<<6)+m;
      float br=u2wr[wix], bi=u2wi[wix];
      re += a.x*br - a.y*bi;
      im += a.x*bi + a.y*br;
    }
    sF[tid]=make_float2(re,im);
  }
  __syncthreads();
  for (int id=tid; id<2048; id+=256){
    int o=id>>9, rem=id&511, r=rem>>3, kx=rem&7;
    float re=0.f, im=0.f;
    #pragma unroll
    for (int ky=0;ky<8;ky++){
      int j=(ky*r)&63; float cc=twc[j], ss=tws[j];
      float2 f=sF[o*64+ky*8+kx];
      re += f.x*cc - f.y*ss; im += f.x*ss + f.y*cc;
    }
    T[id]=make_float2(re,im);
  }
  __syncthreads();
  const float4* gx4 = (const float4*)(g_x1 + (size_t)n*32*NPIX);
  float* go = out + (size_t)n*4*NPIX;
  const float inv = 1.0f/4096.0f;
  #pragma unroll
  for (int k=0;k<2;k++){
    int q = blockIdx.y*512 + k*256 + tid;   // quad index within image
    int p0 = q*4, r = p0>>6, cb = p0&63;
    float ybuf[4][4];
    #pragma unroll
    for (int j=0;j<4;j++){
      int cc = cb+j;
      u64 a[4]={0ull,0ull,0ull,0ull};
      #pragma unroll
      for (int kx=1;kx<8;kx++){
        u64 wv = twp[(kx*cc)&63];
        #pragma unroll
        for (int o=0;o<4;o++) fma2(a[o], *(const u64*)&T[o*512 + r*8 + kx], wv);
      }
      #pragma unroll
      for (int o=0;o<4;o++){
        float2 v = up(a[o]);
        ybuf[o][j] = T[o*512 + r*8].x + 2.f*(v.x - v.y);
      }
    }
    u64 s01[4]={0ull,0ull,0ull,0ull}, s23[4]={0ull,0ull,0ull,0ull};
    #pragma unroll 8
    for (int ci=0;ci<32;ci++){
      float4 xv = __ldg(gx4 + ci*1024 + q);
      u64 x01 = pk(xv.x,xv.y), x23 = pk(xv.z,xv.w);
      #pragma unroll
      for (int o=0;o<4;o++){
        u64 wv = sw2[o*32+ci];
        fma2(s01[o], wv, x01);
        fma2(s23[o], wv, x23);
      }
    }
    #pragma unroll
    for (int o=0;o<4;o++){
      float2 p01=up(s01[o]), p23=up(s23[o]);
      float bo = sbv[o];
      float4 r4;
      r4.x = ybuf[o][0]*inv + p01.x + bo;
      r4.y = ybuf[o][1]*inv + p01.y + bo;
      r4.z = ybuf[o][2]*inv + p23.x + bo;
      r4.w = ybuf[o][3]*inv + p23.y + bo;
      *(float4*)(go + o*NPIX + p0) = r4;
    }
  }
}

// ---------------- launch ----------------
extern "C" void kernel_launch(void* const* d_in, const int* in_sizes, int n_in,
                              void* d_out, int out_size){
  const float* v   = (const float*)d_in[0];
  const float* qwr = (const float*)d_in[1];
  const float* qwi = (const float*)d_in[2];
  const float* kwr = (const float*)d_in[3];
  const float* kwi = (const float*)d_in[4];
  const float* vwr = (const float*)d_in[5];
  const float* vwi = (const float*)d_in[6];
  const float* u1wr= (const float*)d_in[7];
  const float* u1wi= (const float*)d_in[8];
  const float* u2wr= (const float*)d_in[9];
  const float* u2wi= (const float*)d_in[10];
  const float* s1w = (const float*)d_in[11];
  const float* s1b = (const float*)d_in[12];
  const float* s2w = (const float*)d_in[13];
  const float* s2b = (const float*)d_in[14];

  k_fwd_v  <<<64, 256>>>(v);
  k_qkv    <<<dim3(64,3), 256>>>(qwr,qwi,kwr,kwi,vwr,vwi);
  k_l2s    <<<dim3(16,4), 256>>>();
  k_attn_u <<<dim3(16,8), 256>>>();
  k_u1     <<<dim3(64,4), 256>>>(u1wr,u1wi,s1w);
  k_x1     <<<512, 256>>>(s1b);
  k_final  <<<dim3(64,2), 256>>>(u2wr,u2wi,s2w,s2b,(float*)d_out);
}

// round 3
// speedup vs baseline: 2.1814x; 1.6141x over previous
#include <cuda_runtime.h>
#include <math.h>

#define NPIX   4096
#define NMODE  64
#define NSEQ   64
#define NCH    256

typedef unsigned long long u64;

__device__ __forceinline__ u64 pk(float a, float b){
  u64 r; asm("mov.b64 %0,{%1,%2};" : "=l"(r) : "f"(a), "f"(b)); return r;
}
__device__ __forceinline__ float2 up(u64 v){
  float2 r; asm("mov.b64 {%0,%1},%2;" : "=f"(r.x), "=f"(r.y) : "l"(v)); return r;
}
__device__ __forceinline__ void fma2(u64& d, u64 a, u64 b){
  asm("fma.rn.f32x2 %0,%1,%2,%0;" : "+l"(d) : "l"(a), "l"(b));
}

// branch-free erf, Abramowitz-Stegun 7.1.26, max abs err 1.5e-7
__device__ __forceinline__ float erf_fast(float x){
  float ax = fabsf(x);
  float t  = __frcp_rn(1.0f + 0.3275911f*ax);
  float y  = t*(0.254829592f + t*(-0.284496736f + t*(1.421413741f +
             t*(-1.453152027f + t*1.061405429f))));
  float r  = 1.0f - y*__expf(-ax*ax);
  return copysignf(r, x);
}

// ---------------- scratch ----------------
__device__ __align__(16) float2 g_vf [NSEQ*4*NMODE];
__device__ __align__(16) float2 g_qf [NSEQ*NCH*NMODE];
__device__ __align__(16) float2 g_kf [NSEQ*NCH*NMODE];   // Parseval-weighted
__device__ __align__(16) float2 g_vlf[NSEQ*NCH*NMODE];
__device__ __align__(16) float  g_l2p[8*16*1024];
__device__ __align__(16) float  g_A  [16*32*32];
__device__ __align__(16) float2 g_uf [NSEQ*NCH*NMODE];
__device__ __align__(16) float2 g_uf2[NSEQ*32*NMODE];
__device__ __align__(16) float2 g_sk1[NSEQ*32*NMODE];
__device__ __align__(16) float  g_x1 [NSEQ*32*NPIX];
__device__ __align__(16) float2 g_x1f[NSEQ*32*NMODE];

__device__ __forceinline__ void tw_init(float* twc, float* tws, u64* twp, int tid){
  if (tid < 64){
    float a = 0.09817477042468103f * (float)tid;
    float cc = cosf(a), ss = sinf(a);
    twc[tid]=cc; tws[tid]=ss;
    if (twp) twp[tid]=pk(cc,ss);
  }
}

// ---------------- K1: forward DFT of v ----------------
__global__ __launch_bounds__(256) void k_fwd_v(const float* __restrict__ v){
  __shared__ float twc[64], tws[64];
  __shared__ u64   twp[64];
  __shared__ float2 sC[4*8*64];
  int tid=threadIdx.x, chv=tid>>6, c=tid&63;
  tw_init(twc,tws,twp,tid);
  __syncthreads();
  const float* x = v + (size_t)(blockIdx.x*4 + chv)*NPIX + c;
  u64 C2[8];
  #pragma unroll
  for (int ky=0;ky<8;ky++) C2[ky]=0ull;
  for (int r=0;r<64;r++){
    float xv = __ldg(x + r*64);
    u64 x2 = pk(xv,xv);
    #pragma unroll
    for (int ky=0;ky<8;ky++) fma2(C2[ky], x2, twp[(ky*r)&63]);
  }
  #pragma unroll
  for (int ky=0;ky<8;ky++) sC[(chv*8+ky)*64 + c] = up(C2[ky]);
  __syncthreads();
  {
    int md = tid&63, ky2 = md>>3, kx = md&7;
    float re=0.f, im=0.f;
    const float2* Crow = sC + (chv*8+ky2)*64;
    #pragma unroll 8
    for (int cc=0;cc<64;cc++){
      float2 t = Crow[cc];
      int j=(kx*cc)&63;
      re += t.x*twc[j] - t.y*tws[j];
      im -= t.y*twc[j] + t.x*tws[j];
    }
    g_vf[(size_t)(blockIdx.x*4+chv)*64 + md] = make_float2(re,im);
  }
}

// ---------------- K2: q/k/val spectral weight multiply (2 modes/thread) ----------------
// K gets Parseval weights folded in (m=0: imag zeroed; kx=0 col: 0.5; else 2)
__global__ __launch_bounds__(256) void k_qkv(const float* __restrict__ qwr, const float* __restrict__ qwi,
                      const float* __restrict__ kwr, const float* __restrict__ kwi,
                      const float* __restrict__ vwr, const float* __restrict__ vwi){
  int n = blockIdx.x;
  const float *wr, *wi; float2* dst; bool is_k=false;
  if (blockIdx.y==0){wr=qwr;wi=qwi;dst=g_qf;}
  else if (blockIdx.y==1){wr=kwr;wi=kwi;dst=g_kf;is_k=true;}
  else {wr=vwr;wi=vwi;dst=g_vlf;}
  __shared__ float2 sv[256];
  int tid=threadIdx.x;
  sv[tid] = g_vf[n*256+tid];
  __syncthreads();
  for (int op=tid; op<8192; op+=256){
    int co = op>>5, m2 = op&31, m = m2*2;
    float re0=0.f,im0=0.f,re1=0.f,im1=0.f;
    #pragma unroll
    for (int ci=0;ci<4;ci++){
      float2 a0 = sv[ci*64+m], a1 = sv[ci*64+m+1];
      int wix = ((ci<<8)+co)*64 + m;
      float2 w_r = *(const float2*)&wr[wix];
      float2 w_i = *(const float2*)&wi[wix];
      re0 += a0.x*w_r.x - a0.y*w_i.x;  im0 += a0.x*w_i.x + a0.y*w_r.x;
      re1 += a1.x*w_r.y - a1.y*w_i.y;  im1 += a1.x*w_i.y + a1.y*w_r.y;
    }
    if (is_k){
      if (m2==0){ im0 = 0.f; }                       // (0,0): Re only, weight 1
      else { float wm0 = ((m2&3)==0)?0.5f:2.0f; re0*=wm0; im0*=wm0; }
      re1*=2.0f; im1*=2.0f;                          // odd m: never kx=0
    }
    float4 st = make_float4(re0,im0,re1,im1);
    *(float4*)&dst[(size_t)n*16384 + co*64 + m] = st;
  }
}

// ---------------- K3: l2 as 32x32x4096 real GEMM per head ----------------
// grid (16 bh, 8 ks), 256 thr = 4 kc x (8 ti x 8 tj), 4x4 register tiles
__global__ __launch_bounds__(256) void k_l2g(){
  int bh=blockIdx.x, ks=blockIdx.y;
  int b=bh>>3, hh=bh&7;
  const u64* Qb=(const u64*)g_qf + ((size_t)b*32*256 + hh*32)*64;
  const u64* Kb=(const u64*)g_kf + ((size_t)b*32*256 + hh*32)*64;
  __shared__ u64 pool[4160];
  u64* Qs = pool;          // [32][65]
  u64* Ks = pool + 2080;   // [32][65]
  int tid=threadIdx.x;
  int kc=tid>>6, ti=(tid>>3)&7, tj=tid&7;
  u64 acc[4][4];
  #pragma unroll
  for (int i=0;i<4;i++)
    #pragma unroll
    for (int j=0;j<4;j++) acc[i][j]=0ull;
  for (int ch=0; ch<4; ch++){
    __syncthreads();
    int gbase = ks*256 + ch*64;
    for (int i=tid;i<2048;i+=256){
      int s=i>>6, l=i&63;
      Qs[s*65+l] = Qb[(size_t)s*16384 + gbase + l];
      Ks[s*65+l] = Kb[(size_t)s*16384 + gbase + l];
    }
    __syncthreads();
    int lb = kc*16;
    #pragma unroll
    for (int l=0;l<16;l++){
      u64 q[4], k[4];
      #pragma unroll
      for (int i=0;i<4;i++) q[i]=Qs[(ti*4+i)*65 + lb + l];
      #pragma unroll
      for (int j=0;j<4;j++) k[j]=Ks[(tj*4+j)*65 + lb + l];
      #pragma unroll
      for (int i=0;i<4;i++)
        #pragma unroll
        for (int j=0;j<4;j++) fma2(acc[i][j], q[i], k[j]);
    }
  }
  __syncthreads();
  float* sred = (float*)pool;   // 4096 floats fit
  #pragma unroll
  for (int i=0;i<4;i++)
    #pragma unroll
    for (int j=0;j<4;j++){
      float2 a = up(acc[i][j]);
      sred[kc*1024 + (ti*4+i)*32 + tj*4+j] = a.x + a.y;
    }
  __syncthreads();
  for (int o=tid;o<1024;o+=256){
    float vsum = sred[o]+sred[1024+o]+sred[2048+o]+sred[3072+o];
    g_l2p[(ks*16+bh)*1024 + o] = vsum;
  }
}

// ---------------- K3b: reduce partials + softmax ----------------
__global__ __launch_bounds__(256) void k_soft(){
  int bh=blockIdx.x;
  int tid=threadIdx.x, w=tid>>5, lane=tid&31;
  #pragma unroll
  for (int rr=0; rr<4; rr++){
    int s = w*4+rr;
    float vv = 0.f;
    #pragma unroll
    for (int ks=0;ks<8;ks++) vv += g_l2p[(ks*16+bh)*1024 + s*32 + lane];
    vv *= 2.9802322387695312e-8f;
    float mx = vv;
    #pragma unroll
    for (int o=16;o;o>>=1) mx = fmaxf(mx, __shfl_xor_sync(0xffffffffu, mx, o));
    float e = expf(vv-mx);
    float sm = e;
    #pragma unroll
    for (int o=16;o;o>>=1) sm += __shfl_xor_sync(0xffffffffu, sm, o);
    g_A[bh*1024 + s*32 + lane] = e/sm;
  }
}

// ---------------- K4: U = A @ val ----------------
// grid (16 head, 8 dg, 2 sg), 256 thr
__global__ __launch_bounds__(256) void k_attn_u(){
  int bh = blockIdx.x, dg = blockIdx.y, sg = blockIdx.z;
  int b = bh>>3, hh = bh&7;
  const float2* Vh = g_vlf + (size_t)(b*32 + hh*4)*16384;
  __shared__ float2 sA2[512];        // (a,a), [16 s][32 t]
  int tid = threadIdx.x;
  for (int i=tid;i<512;i+=256){
    int sloc=i>>5, t=i&31;
    float a = g_A[bh*1024 + (sg*16+sloc)*32 + t];
    sA2[i]=make_float2(a,a);
  }
  __syncthreads();
  int d = dg*4 + (tid>>6);
  int m = tid&63;
  u64 acc[16];
  #pragma unroll
  for (int s=0;s<16;s++) acc[s]=0ull;
  const float2* vp = Vh + d*64 + m;
  #pragma unroll 1
  for (int t=0;t<32;t+=4){
    u64 v0 = *(const u64*)(vp + (size_t)(t+0)*2048);
    u64 v1 = *(const u64*)(vp + (size_t)(t+1)*2048);
    u64 v2 = *(const u64*)(vp + (size_t)(t+2)*2048);
    u64 v3 = *(const u64*)(vp + (size_t)(t+3)*2048);
    #pragma unroll
    for (int s=0;s<16;s++){
      fma2(acc[s], *(const u64*)&sA2[s*32+t+0], v0);
      fma2(acc[s], *(const u64*)&sA2[s*32+t+1], v1);
      fma2(acc[s], *(const u64*)&sA2[s*32+t+2], v2);
      fma2(acc[s], *(const u64*)&sA2[s*32+t+3], v3);
    }
  }
  int chb = hh*32 + d;
  #pragma unroll
  for (int s=0;s<16;s++)
    g_uf[(size_t)((b*32+sg*16+s)*256 + chb)*64 + m] = up(acc[s]);
}

// ---------------- K5: per-mode GEMM 256->32 (u1 with P projection) + s1 skip ----------------
__global__ __launch_bounds__(256) void k_u1(const float* __restrict__ u1wr, const float* __restrict__ u1wi,
                     const float* __restrict__ s1w){
  int m = blockIdx.x, ns = blockIdx.y;
  bool kx0 = ((m&7)==0), m0 = (m==0);
  int tid = threadIdx.x;
  int co = tid>>3, ngp = tid&7;
  __shared__ float2 sA [32*16];
  __shared__ float2 sW [32*32];
  __shared__ float2 sWs[32*32];
  __shared__ float  sS [32*32];
  u64 cv0=0ull, cv1=0ull, sv0=0ull, sv1=0ull;
  float pm = (!m0 && kx0) ? 0.5f : 1.0f;
  for (int ci0=0; ci0<256; ci0+=32){
    __syncthreads();
    #pragma unroll
    for (int k=0;k<2;k++){
      int idx = tid + k*256;
      int cil = idx>>4, ng = idx&15;
      sA[cil*16+ng] = g_uf[(size_t)((ns*16+ng)*256 + ci0+cil)*64 + m];
    }
    #pragma unroll
    for (int k=0;k<4;k++){
      int idx = tid + k*256;
      int cil = idx>>5, co_ = idx&31;
      int widx = ((ci0+cil)*32 + co_)*64 + m;
      float wr = u1wr[widx]*pm, wi = u1wi[widx]*pm;
      sW[idx]  = make_float2(wr, wi);
      sWs[idx] = m0 ? make_float2(0.f,0.f) : make_float2(-wi, wr);
      sS[idx]  = s1w[co_*256 + ci0+cil];
    }
    __syncthreads();
    #pragma unroll 4
    for (int cil=0; cil<32; cil++){
      u64 a0v = *(const u64*)&sA[cil*16 + ngp*2];
      u64 a1v = *(const u64*)&sA[cil*16 + ngp*2 + 1];
      u64 w2  = *(const u64*)&sW [cil*32+co];
      u64 w2s = *(const u64*)&sWs[cil*32+co];
      float sw = sS[cil*32+co];
      u64 sw2 = pk(sw,sw);
      float2 a0 = up(a0v), a1 = up(a1v);
      u64 ax0 = pk(a0.x,a0.x), ay0 = pk(a0.y,a0.y);
      u64 ax1 = pk(a1.x,a1.x), ay1 = pk(a1.y,a1.y);
      fma2(cv0, ax0, w2); fma2(cv0, ay0, w2s);
      fma2(cv1, ax1, w2); fma2(cv1, ay1, w2s);
      fma2(sv0, sw2, a0v);
      fma2(sv1, sw2, a1v);
    }
  }
  int n0 = ns*16 + ngp*2;
  g_uf2[(size_t)(n0*32+co)*64+m]     = up(cv0);
  g_uf2[(size_t)((n0+1)*32+co)*64+m] = up(cv1);
  g_sk1[(size_t)(n0*32+co)*64+m]     = up(sv0);
  g_sk1[(size_t)((n0+1)*32+co)*64+m] = up(sv1);
}

// ---------------- K6: synthesis + gelu + skip -> x1, fused forward DFT -> x1f ----------------
__global__ __launch_bounds__(256) void k_x1(const float* __restrict__ s1b){
  __shared__ float twc[64], tws[64];
  __shared__ u64   twp[64];
  __shared__ float2 sF1[256], sF2[256];
  __shared__ float2 sC[4*8*64];
  int tid=threadIdx.x, chv=tid>>6, c=tid&63;
  int ch = blockIdx.x*4 + chv;
  tw_init(twc,tws,twp,tid);
  sF1[tid] = g_uf2[(size_t)blockIdx.x*256 + tid];
  sF2[tid] = g_sk1[(size_t)blockIdx.x*256 + tid];
  __syncthreads();
  u64 U1p[8], U2p[8];
  #pragma unroll
  for (int ky=0;ky<8;ky++){
    float2 f1=sF1[chv*64+ky*8], f2=sF2[chv*64+ky*8];
    float u1x=f1.x, u1y=f1.y, u2x=f2.x, u2y=f2.y;
    #pragma unroll
    for (int kx=1;kx<8;kx++){
      int j=(kx*c)&63; float tc=twc[j], ts=tws[j];
      f1=sF1[chv*64+ky*8+kx]; f2=sF2[chv*64+ky*8+kx];
      u1x += 2.f*(f1.x*tc - f1.y*ts); u1y += 2.f*(f1.x*ts + f1.y*tc);
      u2x += 2.f*(f2.x*tc - f2.y*ts); u2y += 2.f*(f2.x*ts + f2.y*tc);
    }
    U1p[ky]=pk(u1x,u1y); U2p[ky]=pk(u2x,u2y);
  }
  u64 C2[8];
  #pragma unroll
  for (int ky=0;ky<8;ky++) C2[ky]=0ull;
  float bias = s1b[ch&31];
  float* gx = g_x1 + (size_t)ch*NPIX + c;
  const float inv = 1.0f/4096.0f;
  for (int r=0;r<64;r++){
    u64 wp[8];
    #pragma unroll
    for (int ky=0;ky<8;ky++) wp[ky]=twp[(ky*r)&63];
    u64 a1=0ull, a2=0ull;
    #pragma unroll
    for (int ky=0;ky<8;ky++){ fma2(a1,U1p[ky],wp[ky]); fma2(a2,U2p[ky],wp[ky]); }
    float2 v1=up(a1), v2=up(a2);
    float y1=(v1.x - v1.y)*inv;
    float y2=(v2.x - v2.y)*inv;
    float g = 0.5f*y1*(1.f+erf_fast(y1*0.70710678118654752f));
    float val = g + y2 + bias;
    gx[r*64] = val;
    u64 vp2 = pk(val,val);
    #pragma unroll
    for (int ky=0;ky<8;ky++) fma2(C2[ky], vp2, wp[ky]);
  }
  #pragma unroll
  for (int ky=0;ky<8;ky++) sC[(chv*8+ky)*64 + c] = up(C2[ky]);
  __syncthreads();
  {
    int md=tid&63, ky2=md>>3, kx=md&7;
    float re=0.f, im=0.f;
    const float2* Crow = sC + (chv*8+ky2)*64;
    #pragma unroll 8
    for (int cc=0;cc<64;cc++){
      float2 t = Crow[cc];
      int j=(kx*cc)&63;
      re += t.x*twc[j] - t.y*tws[j];
      im -= t.y*twc[j] + t.x*tws[j];
    }
    g_x1f[(size_t)ch*64 + md] = make_float2(re,im);
  }
}

// ---------------- K7: u2 spectral conv + synthesis + conv1x1 skip ----------------
__global__ __launch_bounds__(256) void k_final(const float* __restrict__ u2wr, const float* __restrict__ u2wi,
                        const float* __restrict__ s2w, const float* __restrict__ s2b,
                        float* __restrict__ out){
  int n = blockIdx.x;
  __shared__ float twc[64], tws[64];
  __shared__ u64   twp[64];
  __shared__ float2 sXF[2048];
  __shared__ float2 sF[256];
  __shared__ float2 T[4*512];
  __shared__ u64 sw2[128];
  __shared__ float sbv[4];
  int tid=threadIdx.x;
  tw_init(twc,tws,twp,tid);
  for (int i=tid;i<2048;i+=256) sXF[i] = g_x1f[(size_t)n*2048 + i];
  if (tid<128){ float w=s2w[tid]; sw2[tid]=pk(w,w); }
  if (tid<4) sbv[tid]=s2b[tid];
  __syncthreads();
  {
    int o=tid>>6, m=tid&63;
    float re=0.f, im=0.f;
    #pragma unroll 8
    for (int ci=0;ci<32;ci++){
      float2 a = sXF[ci*64+m];
      int wix = ((ci*4+o)<<6)+m;
      float br=u2wr[wix], bi=u2wi[wix];
      re += a.x*br - a.y*bi;
      im += a.x*bi + a.y*br;
    }
    sF[tid]=make_float2(re,im);
  }
  __syncthreads();
  for (int id=tid; id<2048; id+=256){
    int o=id>>9, rem=id&511, r=rem>>3, kx=rem&7;
    float re=0.f, im=0.f;
    #pragma unroll
    for (int ky=0;ky<8;ky++){
      int j=(ky*r)&63; float cc=twc[j], ss=tws[j];
      float2 f=sF[o*64+ky*8+kx];
      re += f.x*cc - f.y*ss; im += f.x*ss + f.y*cc;
    }
    T[id]=make_float2(re,im);
  }
  __syncthreads();
  const float4* gx4 = (const float4*)(g_x1 + (size_t)n*32*NPIX);
  float* go = out + (size_t)n*4*NPIX;
  const float inv = 1.0f/4096.0f;
  #pragma unroll
  for (int k=0;k<2;k++){
    int q = blockIdx.y*512 + k*256 + tid;
    int p0 = q*4, r = p0>>6, cb = p0&63;
    float ybuf[4][4];
    #pragma unroll
    for (int j=0;j<4;j++){
      int cc = cb+j;
      u64 a[4]={0ull,0ull,0ull,0ull};
      #pragma unroll
      for (int kx=1;kx<8;kx++){
        u64 wv = twp[(kx*cc)&63];
        #pragma unroll
        for (int o=0;o<4;o++) fma2(a[o], *(const u64*)&T[o*512 + r*8 + kx], wv);
      }
      #pragma unroll
      for (int o=0;o<4;o++){
        float2 v = up(a[o]);
        ybuf[o][j] = T[o*512 + r*8].x + 2.f*(v.x - v.y);
      }
    }
    u64 s01[4]={0ull,0ull,0ull,0ull}, s23[4]={0ull,0ull,0ull,0ull};
    #pragma unroll 8
    for (int ci=0;ci<32;ci++){
      float4 xv = __ldg(gx4 + ci*1024 + q);
      u64 x01 = pk(xv.x,xv.y), x23 = pk(xv.z,xv.w);
      #pragma unroll
      for (int o=0;o<4;o++){
        u64 wv = sw2[o*32+ci];
        fma2(s01[o], wv, x01);
        fma2(s23[o], wv, x23);
      }
    }
    #pragma unroll
    for (int o=0;o<4;o++){
      float2 p01=up(s01[o]), p23=up(s23[o]);
      float bo = sbv[o];
      float4 r4;
      r4.x = ybuf[o][0]*inv + p01.x + bo;
      r4.y = ybuf[o][1]*inv + p01.y + bo;
      r4.z = ybuf[o][2]*inv + p23.x + bo;
      r4.w = ybuf[o][3]*inv + p23.y + bo;
      *(float4*)(go + o*NPIX + p0) = r4;
    }
  }
}

// ---------------- launch ----------------
extern "C" void kernel_launch(void* const* d_in, const int* in_sizes, int n_in,
                              void* d_out, int out_size){
  const float* v   = (const float*)d_in[0];
  const float* qwr = (const float*)d_in[1];
  const float* qwi = (const float*)d_in[2];
  const float* kwr = (const float*)d_in[3];
  const float* kwi = (const float*)d_in[4];
  const float* vwr = (const float*)d_in[5];
  const float* vwi = (const float*)d_in[6];
  const float* u1wr= (const float*)d_in[7];
  const float* u1wi= (const float*)d_in[8];
  const float* u2wr= (const float*)d_in[9];
  const float* u2wi= (const float*)d_in[10];
  const float* s1w = (const float*)d_in[11];
  const float* s1b = (const float*)d_in[12];
  const float* s2w = (const float*)d_in[13];
  const float* s2b = (const float*)d_in[14];

  k_fwd_v  <<<64, 256>>>(v);
  k_qkv    <<<dim3(64,3), 256>>>(qwr,qwi,kwr,kwi,vwr,vwi);
  k_l2g    <<<dim3(16,8), 256>>>();
  k_soft   <<<16, 256>>>();
  k_attn_u <<<dim3(16,8,2), 256>>>();
  k_u1     <<<dim3(64,4), 256>>>(u1wr,u1wi,s1w);
  k_x1     <<<512, 256>>>(s1b);
  k_final  <<<dim3(64,2), 256>>>(u2wr,u2wi,s2w,s2b,(float*)d_out);
}

// round 4
// speedup vs baseline: 2.3564x; 1.0802x over previous
#include <cuda_runtime.h>
#include <math.h>

#define NPIX   4096
#define NMODE  64
#define NSEQ   64
#define NCH    256

typedef unsigned long long u64;

__device__ __forceinline__ u64 pk(float a, float b){
  u64 r; asm("mov.b64 %0,{%1,%2};" : "=l"(r) : "f"(a), "f"(b)); return r;
}
__device__ __forceinline__ float2 up(u64 v){
  float2 r; asm("mov.b64 {%0,%1},%2;" : "=f"(r.x), "=f"(r.y) : "l"(v)); return r;
}
__device__ __forceinline__ void fma2(u64& d, u64 a, u64 b){
  asm("fma.rn.f32x2 %0,%1,%2,%0;" : "+l"(d) : "l"(a), "l"(b));
}

// branch-free erf, Abramowitz-Stegun 7.1.26, max abs err 1.5e-7
__device__ __forceinline__ float erf_fast(float x){
  float ax = fabsf(x);
  float t  = __frcp_rn(1.0f + 0.3275911f*ax);
  float y  = t*(0.254829592f + t*(-0.284496736f + t*(1.421413741f +
             t*(-1.453152027f + t*1.061405429f))));
  float r  = 1.0f - y*__expf(-ax*ax);
  return copysignf(r, x);
}

// ---------------- scratch ----------------
__device__ __align__(16) float2 g_vf [NSEQ*4*NMODE];
__device__ __align__(16) float2 g_qf [NSEQ*NCH*NMODE];
__device__ __align__(16) float2 g_kf [NSEQ*NCH*NMODE];   // Parseval-weighted
__device__ __align__(16) float2 g_vlf[NSEQ*NCH*NMODE];
__device__ __align__(16) float  g_l2p[8*16*1024];
__device__ __align__(16) float2 g_uf [NSEQ*NCH*NMODE];
__device__ __align__(16) float2 g_uf2[NSEQ*32*NMODE];
__device__ __align__(16) float2 g_sk1[NSEQ*32*NMODE];
__device__ __align__(16) float  g_x1 [NSEQ*32*NPIX];
__device__ __align__(16) float2 g_x1f[NSEQ*32*NMODE];

__device__ __forceinline__ void tw_init(float* twc, float* tws, u64* twp, int tid){
  if (tid < 64){
    float a = 0.09817477042468103f * (float)tid;
    float cc = cosf(a), ss = sinf(a);
    twc[tid]=cc; tws[tid]=ss;
    if (twp) twp[tid]=pk(cc,ss);
  }
}

// ---------------- K1: forward DFT of v ----------------
__global__ __launch_bounds__(256) void k_fwd_v(const float* __restrict__ v){
  __shared__ float twc[64], tws[64];
  __shared__ u64   twp[64];
  __shared__ float2 sC[4*8*64];
  int tid=threadIdx.x, chv=tid>>6, c=tid&63;
  tw_init(twc,tws,twp,tid);
  __syncthreads();
  const float* x = v + (size_t)(blockIdx.x*4 + chv)*NPIX + c;
  u64 C2[8];
  #pragma unroll
  for (int ky=0;ky<8;ky++) C2[ky]=0ull;
  for (int r=0;r<64;r++){
    float xv = __ldg(x + r*64);
    u64 x2 = pk(xv,xv);
    #pragma unroll
    for (int ky=0;ky<8;ky++) fma2(C2[ky], x2, twp[(ky*r)&63]);
  }
  #pragma unroll
  for (int ky=0;ky<8;ky++) sC[(chv*8+ky)*64 + c] = up(C2[ky]);
  __syncthreads();
  {
    int md = tid&63, ky2 = md>>3, kx = md&7;
    float re=0.f, im=0.f;
    const float2* Crow = sC + (chv*8+ky2)*64;
    #pragma unroll 8
    for (int cc=0;cc<64;cc++){
      float2 t = Crow[cc];
      int j=(kx*cc)&63;
      re += t.x*twc[j] - t.y*tws[j];
      im -= t.y*twc[j] + t.x*tws[j];
    }
    g_vf[(size_t)(blockIdx.x*4+chv)*64 + md] = make_float2(re,im);
  }
}

// ---------------- K2: q/k/val spectral weight multiply, 4-n weight reuse ----------------
// grid (16 ngroup, 3 tensor, 4 cogroup), 256 thr
__global__ __launch_bounds__(256) void k_qkv(const float* __restrict__ qwr, const float* __restrict__ qwi,
                      const float* __restrict__ kwr, const float* __restrict__ kwi,
                      const float* __restrict__ vwr, const float* __restrict__ vwi){
  int ng = blockIdx.x, cog = blockIdx.z;
  const float *wr, *wi; float2* dst; bool is_k=false;
  if (blockIdx.y==0){wr=qwr;wi=qwi;dst=g_qf;}
  else if (blockIdx.y==1){wr=kwr;wi=kwi;dst=g_kf;is_k=true;}
  else {wr=vwr;wi=vwi;dst=g_vlf;}
  __shared__ float2 sv[1024];           // vf for 4 n
  int tid=threadIdx.x;
  int n0 = ng*4;
  for (int i=tid;i<1024;i+=256) sv[i] = g_vf[(size_t)n0*256 + i];
  __syncthreads();
  for (int p=tid; p<2048; p+=256){
    int co_l = p>>5, m2 = p&31, m = m2*2;
    int co = cog*64 + co_l;
    float2 wrv[4], wiv[4];
    #pragma unroll
    for (int ci=0;ci<4;ci++){
      int wix = ((ci<<8)+co)*64 + m;
      wrv[ci] = *(const float2*)&wr[wix];
      wiv[ci] = *(const float2*)&wi[wix];
    }
    #pragma unroll
    for (int nl=0;nl<4;nl++){
      float re0=0.f,im0=0.f,re1=0.f,im1=0.f;
      #pragma unroll
      for (int ci=0;ci<4;ci++){
        float2 a0 = sv[nl*256+ci*64+m], a1 = sv[nl*256+ci*64+m+1];
        re0 += a0.x*wrv[ci].x - a0.y*wiv[ci].x;  im0 += a0.x*wiv[ci].x + a0.y*wrv[ci].x;
        re1 += a1.x*wrv[ci].y - a1.y*wiv[ci].y;  im1 += a1.x*wiv[ci].y + a1.y*wrv[ci].y;
      }
      if (is_k){
        if (m2==0){ im0 = 0.f; }                       // (0,0): Re only, weight 1
        else { float wm0 = ((m2&3)==0)?0.5f:2.0f; re0*=wm0; im0*=wm0; }
        re1*=2.0f; im1*=2.0f;                          // odd m: never kx=0
      }
      float4 st = make_float4(re0,im0,re1,im1);
      *(float4*)&dst[(size_t)(n0+nl)*16384 + co*64 + m] = st;
    }
  }
}

// ---------------- K3: l2 as 32x32x4096 real GEMM per head (k-split partials) ----------------
// grid (16 bh, 8 ks), 256 thr = 4 kc x (8 ti x 8 tj), 4x4 register tiles
__global__ __launch_bounds__(256) void k_l2g(){
  int bh=blockIdx.x, ks=blockIdx.y;
  int b=bh>>3, hh=bh&7;
  const u64* Qb=(const u64*)g_qf + ((size_t)b*32*256 + hh*32)*64;
  const u64* Kb=(const u64*)g_kf + ((size_t)b*32*256 + hh*32)*64;
  __shared__ u64 pool[4160];
  u64* Qs = pool;          // [32][65]
  u64* Ks = pool + 2080;   // [32][65]
  int tid=threadIdx.x;
  int kc=tid>>6, ti=(tid>>3)&7, tj=tid&7;
  u64 acc[4][4];
  #pragma unroll
  for (int i=0;i<4;i++)
    #pragma unroll
    for (int j=0;j<4;j++) acc[i][j]=0ull;
  for (int ch=0; ch<4; ch++){
    __syncthreads();
    int gbase = ks*256 + ch*64;
    for (int i=tid;i<2048;i+=256){
      int s=i>>6, l=i&63;
      Qs[s*65+l] = Qb[(size_t)s*16384 + gbase + l];
      Ks[s*65+l] = Kb[(size_t)s*16384 + gbase + l];
    }
    __syncthreads();
    int lb = kc*16;
    #pragma unroll
    for (int l=0;l<16;l++){
      u64 q[4], k[4];
      #pragma unroll
      for (int i=0;i<4;i++) q[i]=Qs[(ti*4+i)*65 + lb + l];
      #pragma unroll
      for (int j=0;j<4;j++) k[j]=Ks[(tj*4+j)*65 + lb + l];
      #pragma unroll
      for (int i=0;i<4;i++)
        #pragma unroll
        for (int j=0;j<4;j++) fma2(acc[i][j], q[i], k[j]);
    }
  }
  __syncthreads();
  float* sred = (float*)pool;
  #pragma unroll
  for (int i=0;i<4;i++)
    #pragma unroll
    for (int j=0;j<4;j++){
      float2 a = up(acc[i][j]);
      sred[kc*1024 + (ti*4+i)*32 + tj*4+j] = a.x + a.y;
    }
  __syncthreads();
  for (int o=tid;o<1024;o+=256){
    float vsum = sred[o]+sred[1024+o]+sred[2048+o]+sred[3072+o];
    g_l2p[(ks*16+bh)*1024 + o] = vsum;
  }
}

// ---------------- K4: fused partial-reduce + softmax + U = A @ val ----------------
// grid (16 head, 8 dg, 2 sg), 256 thr
__global__ __launch_bounds__(256) void k_attn_u(){
  int bh = blockIdx.x, dg = blockIdx.y, sg = blockIdx.z;
  int b = bh>>3, hh = bh&7;
  const float2* Vh = g_vlf + (size_t)(b*32 + hh*4)*16384;
  __shared__ float  sL [512];        // logits, [16 s][32 t]
  __shared__ float2 sA2[512];        // softmax probs (p,p)
  int tid = threadIdx.x;
  // reduce k-split partials for our 16 s rows
  for (int i=tid;i<512;i+=256){
    int sl=i>>5, t=i&31;
    float vsum = 0.f;
    #pragma unroll
    for (int ks=0;ks<8;ks++)
      vsum += g_l2p[(ks*16+bh)*1024 + (sg*16+sl)*32 + t];
    sL[i] = vsum * 2.9802322387695312e-8f;   // 0.5 * dx^2 * 1/N (Parseval)
  }
  __syncthreads();
  // softmax: warp w handles rows 2w, 2w+1
  {
    int w=tid>>5, lane=tid&31;
    #pragma unroll
    for (int rr=0;rr<2;rr++){
      int sl = w*2+rr;
      float x = sL[sl*32+lane];
      float mx = x;
      #pragma unroll
      for (int o=16;o;o>>=1) mx = fmaxf(mx, __shfl_xor_sync(0xffffffffu, mx, o));
      float e = expf(x-mx);
      float sm = e;
      #pragma unroll
      for (int o=16;o;o>>=1) sm += __shfl_xor_sync(0xffffffffu, sm, o);
      float pr = e/sm;
      sA2[sl*32+lane] = make_float2(pr,pr);
    }
  }
  __syncthreads();
  int d = dg*4 + (tid>>6);
  int m = tid&63;
  u64 acc[16];
  #pragma unroll
  for (int s=0;s<16;s++) acc[s]=0ull;
  const float2* vp = Vh + d*64 + m;
  #pragma unroll 1
  for (int t=0;t<32;t+=4){
    u64 v0 = *(const u64*)(vp + (size_t)(t+0)*2048);
    u64 v1 = *(const u64*)(vp + (size_t)(t+1)*2048);
    u64 v2 = *(const u64*)(vp + (size_t)(t+2)*2048);
    u64 v3 = *(const u64*)(vp + (size_t)(t+3)*2048);
    #pragma unroll
    for (int s=0;s<16;s++){
      fma2(acc[s], *(const u64*)&sA2[s*32+t+0], v0);
      fma2(acc[s], *(const u64*)&sA2[s*32+t+1], v1);
      fma2(acc[s], *(const u64*)&sA2[s*32+t+2], v2);
      fma2(acc[s], *(const u64*)&sA2[s*32+t+3], v3);
    }
  }
  int chb = hh*32 + d;
  #pragma unroll
  for (int s=0;s<16;s++)
    g_uf[(size_t)((b*32+sg*16+s)*256 + chb)*64 + m] = up(acc[s]);
}

// ---------------- K5: per-mode GEMM 256->32 (u1 with P projection) + s1 skip ----------------
__global__ __launch_bounds__(256) void k_u1(const float* __restrict__ u1wr, const float* __restrict__ u1wi,
                     const float* __restrict__ s1w){
  int m = blockIdx.x, ns = blockIdx.y;
  bool kx0 = ((m&7)==0), m0 = (m==0);
  int tid = threadIdx.x;
  int co = tid>>3, ngp = tid&7;
  __shared__ float2 sA [32*16];
  __shared__ float2 sW [32*32];
  __shared__ float2 sWs[32*32];
  __shared__ float  sS [32*32];
  u64 cv0=0ull, cv1=0ull, sv0=0ull, sv1=0ull;
  float pm = (!m0 && kx0) ? 0.5f : 1.0f;
  for (int ci0=0; ci0<256; ci0+=32){
    __syncthreads();
    #pragma unroll
    for (int k=0;k<2;k++){
      int idx = tid + k*256;
      int cil = idx>>4, ng = idx&15;
      sA[cil*16+ng] = g_uf[(size_t)((ns*16+ng)*256 + ci0+cil)*64 + m];
    }
    #pragma unroll
    for (int k=0;k<4;k++){
      int idx = tid + k*256;
      int cil = idx>>5, co_ = idx&31;
      int widx = ((ci0+cil)*32 + co_)*64 + m;
      float wr = u1wr[widx]*pm, wi = u1wi[widx]*pm;
      sW[idx]  = make_float2(wr, wi);
      sWs[idx] = m0 ? make_float2(0.f,0.f) : make_float2(-wi, wr);
      sS[idx]  = s1w[co_*256 + ci0+cil];
    }
    __syncthreads();
    #pragma unroll 4
    for (int cil=0; cil<32; cil++){
      u64 a0v = *(const u64*)&sA[cil*16 + ngp*2];
      u64 a1v = *(const u64*)&sA[cil*16 + ngp*2 + 1];
      u64 w2  = *(const u64*)&sW [cil*32+co];
      u64 w2s = *(const u64*)&sWs[cil*32+co];
      float sw = sS[cil*32+co];
      u64 sw2 = pk(sw,sw);
      float2 a0 = up(a0v), a1 = up(a1v);
      u64 ax0 = pk(a0.x,a0.x), ay0 = pk(a0.y,a0.y);
      u64 ax1 = pk(a1.x,a1.x), ay1 = pk(a1.y,a1.y);
      fma2(cv0, ax0, w2); fma2(cv0, ay0, w2s);
      fma2(cv1, ax1, w2); fma2(cv1, ay1, w2s);
      fma2(sv0, sw2, a0v);
      fma2(sv1, sw2, a1v);
    }
  }
  int n0 = ns*16 + ngp*2;
  g_uf2[(size_t)(n0*32+co)*64+m]     = up(cv0);
  g_uf2[(size_t)((n0+1)*32+co)*64+m] = up(cv1);
  g_sk1[(size_t)(n0*32+co)*64+m]     = up(sv0);
  g_sk1[(size_t)((n0+1)*32+co)*64+m] = up(sv1);
}

// ---------------- K6: synthesis + gelu + skip -> x1, fused forward DFT -> x1f ----------------
__global__ __launch_bounds__(256) void k_x1(const float* __restrict__ s1b){
  __shared__ float twc[64], tws[64];
  __shared__ u64   twp[64];
  __shared__ float2 sF1[256], sF2[256];
  __shared__ float2 sC[4*8*64];
  int tid=threadIdx.x, chv=tid>>6, c=tid&63;
  int ch = blockIdx.x*4 + chv;
  tw_init(twc,tws,twp,tid);
  sF1[tid] = g_uf2[(size_t)blockIdx.x*256 + tid];
  sF2[tid] = g_sk1[(size_t)blockIdx.x*256 + tid];
  __syncthreads();
  u64 U1p[8], U2p[8];
  #pragma unroll
  for (int ky=0;ky<8;ky++){
    float2 f1=sF1[chv*64+ky*8], f2=sF2[chv*64+ky*8];
    float u1x=f1.x, u1y=f1.y, u2x=f2.x, u2y=f2.y;
    #pragma unroll
    for (int kx=1;kx<8;kx++){
      int j=(kx*c)&63; float tc=twc[j], ts=tws[j];
      f1=sF1[chv*64+ky*8+kx]; f2=sF2[chv*64+ky*8+kx];
      u1x += 2.f*(f1.x*tc - f1.y*ts); u1y += 2.f*(f1.x*ts + f1.y*tc);
      u2x += 2.f*(f2.x*tc - f2.y*ts); u2y += 2.f*(f2.x*ts + f2.y*tc);
    }
    U1p[ky]=pk(u1x,u1y); U2p[ky]=pk(u2x,u2y);
  }
  u64 C2[8];
  #pragma unroll
  for (int ky=0;ky<8;ky++) C2[ky]=0ull;
  float bias = s1b[ch&31];
  float* gx = g_x1 + (size_t)ch*NPIX + c;
  const float inv = 1.0f/4096.0f;
  for (int r=0;r<64;r++){
    u64 wp[8];
    #pragma unroll
    for (int ky=0;ky<8;ky++) wp[ky]=twp[(ky*r)&63];
    u64 a1=0ull, a2=0ull;
    #pragma unroll
    for (int ky=0;ky<8;ky++){ fma2(a1,U1p[ky],wp[ky]); fma2(a2,U2p[ky],wp[ky]); }
    float2 v1=up(a1), v2=up(a2);
    float y1=(v1.x - v1.y)*inv;
    float y2=(v2.x - v2.y)*inv;
    float g = 0.5f*y1*(1.f+erf_fast(y1*0.70710678118654752f));
    float val = g + y2 + bias;
    gx[r*64] = val;
    u64 vp2 = pk(val,val);
    #pragma unroll
    for (int ky=0;ky<8;ky++) fma2(C2[ky], vp2, wp[ky]);
  }
  #pragma unroll
  for (int ky=0;ky<8;ky++) sC[(chv*8+ky)*64 + c] = up(C2[ky]);
  __syncthreads();
  {
    int md=tid&63, ky2=md>>3, kx=md&7;
    float re=0.f, im=0.f;
    const float2* Crow = sC + (chv*8+ky2)*64;
    #pragma unroll 8
    for (int cc=0;cc<64;cc++){
      float2 t = Crow[cc];
      int j=(kx*cc)&63;
      re += t.x*twc[j] - t.y*tws[j];
      im -= t.y*twc[j] + t.x*tws[j];
    }
    g_x1f[(size_t)ch*64 + md] = make_float2(re,im);
  }
}

// ---------------- K7: u2 spectral conv + synthesis + conv1x1 skip ----------------
__global__ __launch_bounds__(256) void k_final(const float* __restrict__ u2wr, const float* __restrict__ u2wi,
                        const float* __restrict__ s2w, const float* __restrict__ s2b,
                        float* __restrict__ out){
  int n = blockIdx.x;
  __shared__ float twc[64], tws[64];
  __shared__ u64   twp[64];
  __shared__ float2 sXF[2048];
  __shared__ float2 sF[256];
  __shared__ float2 T[4*512];
  __shared__ u64 sw2[128];
  __shared__ float sbv[4];
  int tid=threadIdx.x;
  tw_init(twc,tws,twp,tid);
  for (int i=tid;i<2048;i+=256) sXF[i] = g_x1f[(size_t)n*2048 + i];
  if (tid<128){ float w=s2w[tid]; sw2[tid]=pk(w,w); }
  if (tid<4) sbv[tid]=s2b[tid];
  __syncthreads();
  {
    int o=tid>>6, m=tid&63;
    float re=0.f, im=0.f;
    #pragma unroll 8
    for (int ci=0;ci<32;ci++){
      float2 a = sXF[ci*64+m];
      int wix = ((ci*4+o)<<6)+m;
      float br=u2wr[wix], bi=u2wi[wix];
      re += a.x*br - a.y*bi;
      im += a.x*bi + a.y*br;
    }
    sF[tid]=make_float2(re,im);
  }
  __syncthreads();
  for (int id=tid; id<2048; id+=256){
    int o=id>>9, rem=id&511, r=rem>>3, kx=rem&7;
    float re=0.f, im=0.f;
    #pragma unroll
    for (int ky=0;ky<8;ky++){
      int j=(ky*r)&63; float cc=twc[j], ss=tws[j];
      float2 f=sF[o*64+ky*8+kx];
      re += f.x*cc - f.y*ss; im += f.x*ss + f.y*cc;
    }
    T[id]=make_float2(re,im);
  }
  __syncthreads();
  const float4* gx4 = (const float4*)(g_x1 + (size_t)n*32*NPIX);
  float* go = out + (size_t)n*4*NPIX;
  const float inv = 1.0f/4096.0f;
  #pragma unroll
  for (int k=0;k<2;k++){
    int q = blockIdx.y*512 + k*256 + tid;
    int p0 = q*4, r = p0>>6, cb = p0&63;
    float ybuf[4][4];
    #pragma unroll
    for (int j=0;j<4;j++){
      int cc = cb+j;
      u64 a[4]={0ull,0ull,0ull,0ull};
      #pragma unroll
      for (int kx=1;kx<8;kx++){
        u64 wv = twp[(kx*cc)&63];
        #pragma unroll
        for (int o=0;o<4;o++) fma2(a[o], *(const u64*)&T[o*512 + r*8 + kx], wv);
      }
      #pragma unroll
      for (int o=0;o<4;o++){
        float2 v = up(a[o]);
        ybuf[o][j] = T[o*512 + r*8].x + 2.f*(v.x - v.y);
      }
    }
    u64 s01[4]={0ull,0ull,0ull,0ull}, s23[4]={0ull,0ull,0ull,0ull};
    #pragma unroll 8
    for (int ci=0;ci<32;ci++){
      float4 xv = __ldg(gx4 + ci*1024 + q);
      u64 x01 = pk(xv.x,xv.y), x23 = pk(xv.z,xv.w);
      #pragma unroll
      for (int o=0;o<4;o++){
        u64 wv = sw2[o*32+ci];
        fma2(s01[o], wv, x01);
        fma2(s23[o], wv, x23);
      }
    }
    #pragma unroll
    for (int o=0;o<4;o++){
      float2 p01=up(s01[o]), p23=up(s23[o]);
      float bo = sbv[o];
      float4 r4;
      r4.x = ybuf[o][0]*inv + p01.x + bo;
      r4.y = ybuf[o][1]*inv + p01.y + bo;
      r4.z = ybuf[o][2]*inv + p23.x + bo;
      r4.w = ybuf[o][3]*inv + p23.y + bo;
      *(float4*)(go + o*NPIX + p0) = r4;
    }
  }
}

// ---------------- launch ----------------
extern "C" void kernel_launch(void* const* d_in, const int* in_sizes, int n_in,
                              void* d_out, int out_size){
  const float* v   = (const float*)d_in[0];
  const float* qwr = (const float*)d_in[1];
  const float* qwi = (const float*)d_in[2];
  const float* kwr = (const float*)d_in[3];
  const float* kwi = (const float*)d_in[4];
  const float* vwr = (const float*)d_in[5];
  const float* vwi = (const float*)d_in[6];
  const float* u1wr= (const float*)d_in[7];
  const float* u1wi= (const float*)d_in[8];
  const float* u2wr= (const float*)d_in[9];
  const float* u2wi= (const float*)d_in[10];
  const float* s1w = (const float*)d_in[11];
  const float* s1b = (const float*)d_in[12];
  const float* s2w = (const float*)d_in[13];
  const float* s2b = (const float*)d_in[14];

  k_fwd_v  <<<64, 256>>>(v);
  k_qkv    <<<dim3(16,3,4), 256>>>(qwr,qwi,kwr,kwi,vwr,vwi);
  k_l2g    <<<dim3(16,8), 256>>>();
  k_attn_u <<<dim3(16,8,2), 256>>>();
  k_u1     <<<dim3(64,4), 256>>>(u1wr,u1wi,s1w);
  k_x1     <<<512, 256>>>(s1b);
  k_final  <<<dim3(64,2), 256>>>(u2wr,u2wi,s2w,s2b,(float*)d_out);
}